// round 15
// baseline (speedup 1.0000x reference)
#include <cuda_runtime.h>
#include <cuda_bf16.h>
#include <math.h>
#include <float.h>
#include <stdint.h>

#define NPART 62
#define MM    512
#define DD    256
#define MARGIN 0.2f
#define NTILE 36           // all pairs (a<=b)
#define NOFF  28           // off-diagonal pairs (a<b)

// ---- offdiag smem (R14 layout) ----
#define PLANE   4096       // 64 * 64
#define BUFSZ   16384      // 4 planes
#define SM_SQ     32768
#define SM_ROWMIN 33280
#define SM_ROWMAX 33792
#define SM_COLMIN 34304
#define SM_RSUM   34816
#define SM_TOTAL  35328

// ---- diag smem: 8 chunks x (hi 4KB + lo 4KB) = 64KB + scratch ----
#define D_CHUNK  8192
#define D_SQ     65536     // 64 floats
#define D_ROWMIN 65792     // 128 f
#define D_ROWMAX 66304     // 128 f
#define D_RSUM   66816     // 8 f
#define D_TOTAL  67584

// global scratch (no allocation allowed)
__device__ float g_min[NPART * 64 * 64];
__device__ float g_hp[NPART * MM];
__device__ float g_dsum[NPART * NTILE];
__device__ int   g_cnt[NPART];
__device__ __align__(16) __nv_bfloat16 g_hi[(size_t)NPART * MM * DD];
__device__ __align__(16) __nv_bfloat16 g_lo[(size_t)NPART * MM * DD];
__device__ __align__(16) float g_sq[NPART * MM];

__device__ __forceinline__ uint32_t smem_u32(const void* p) {
    uint32_t a;
    asm("{ .reg .u64 t; cvta.to.shared.u64 t, %1; cvt.u32.u64 %0, t; }" : "=r"(a) : "l"(p));
    return a;
}
__device__ __forceinline__ void cp16(uint32_t dst, const void* src) {
    asm volatile("cp.async.cg.shared.global [%0], [%1], 16;" :: "r"(dst), "l"(src));
}
#define CP_COMMIT() asm volatile("cp.async.commit_group;" ::: "memory")
#define CP_WAIT(n)  asm volatile("cp.async.wait_group %0;" :: "n"(n) : "memory")

__device__ __forceinline__ void ldm_x4(uint32_t* r, uint32_t addr) {
    asm volatile("ldmatrix.sync.aligned.m8n8.x4.shared.b16 {%0,%1,%2,%3}, [%4];"
                 : "=r"(r[0]), "=r"(r[1]), "=r"(r[2]), "=r"(r[3]) : "r"(addr));
}
__device__ __forceinline__ void mma16816(float* c, const uint32_t* a, const uint32_t* b) {
    asm volatile("mma.sync.aligned.m16n8k16.row.col.f32.bf16.bf16.f32 "
                 "{%0,%1,%2,%3}, {%4,%5,%6,%7}, {%8,%9}, {%0,%1,%2,%3};"
                 : "+f"(c[0]), "+f"(c[1]), "+f"(c[2]), "+f"(c[3])
                 : "r"(a[0]), "r"(a[1]), "r"(a[2]), "r"(a[3]), "r"(b[0]), "r"(b[1]));
}
__device__ __forceinline__ void tile_pair(int t, int& a, int& b) {
    int aa = 0, tt = t;
    while (tt >= 8 - aa) { tt -= 8 - aa; aa++; }
    a = aa; b = aa + tt;
}
// 8 floats -> uint4 hi + uint4 lo (+exact sq accum)
__device__ __forceinline__ void split8(float4 v0, float4 v1, uint4& hi, uint4& lo,
                                       float& sq) {
    __nv_bfloat162 h0 = __floats2bfloat162_rn(v0.x, v0.y);
    __nv_bfloat162 h1 = __floats2bfloat162_rn(v0.z, v0.w);
    __nv_bfloat162 h2 = __floats2bfloat162_rn(v1.x, v1.y);
    __nv_bfloat162 h3 = __floats2bfloat162_rn(v1.z, v1.w);
    float2 f0 = __bfloat1622float2(h0), f1 = __bfloat1622float2(h1);
    float2 f2 = __bfloat1622float2(h2), f3 = __bfloat1622float2(h3);
    __nv_bfloat162 l0 = __floats2bfloat162_rn(v0.x - f0.x, v0.y - f0.y);
    __nv_bfloat162 l1 = __floats2bfloat162_rn(v0.z - f1.x, v0.w - f1.y);
    __nv_bfloat162 l2 = __floats2bfloat162_rn(v1.x - f2.x, v1.y - f2.y);
    __nv_bfloat162 l3 = __floats2bfloat162_rn(v1.z - f3.x, v1.w - f3.y);
    hi = make_uint4(*(uint32_t*)&h0, *(uint32_t*)&h1, *(uint32_t*)&h2, *(uint32_t*)&h3);
    lo = make_uint4(*(uint32_t*)&l0, *(uint32_t*)&l1, *(uint32_t*)&l2, *(uint32_t*)&l3);
    sq += v0.x * v0.x + v0.y * v0.y + v0.z * v0.z + v0.w * v0.w
        + v1.x * v1.x + v1.y * v1.y + v1.z * v1.z + v1.w * v1.w;
}

// ---------------------------------------------------------------------------
// Kernel 1: diagonal tiles + conversion. CTA = (group a, part n).
// Converts its 64 rows fp32 -> split-bf16 straight into smem (full K),
// publishes hi/lo/sq to global for kernel 2, then computes the (a,a) gram
// tile from smem (no cp.async, no mainloop barriers).
// ---------------------------------------------------------------------------
__global__ void __launch_bounds__(128, 3) diag_kernel(const float* __restrict__ f) {
    extern __shared__ char smem[];
    uint32_t sb = smem_u32(smem);
    const int tid  = threadIdx.x;
    const int wid  = tid >> 5;
    const int lane = tid & 31;
    const int wr = wid >> 1;
    const int wc = wid & 1;
    const int a = blockIdx.x;
    const int n = blockIdx.y;

    // ---- convert phase ----
    {
        const int row = tid >> 1, h = tid & 1;
        const size_t grow = (size_t)n * MM + a * 64 + row;
        const float* src = f + grow * DD + h * 16;
        const uint32_t sw0 = (uint32_t)(((h * 2 + 0) ^ (row >> 1)) & 3) << 4;
        const uint32_t sw1 = (uint32_t)(((h * 2 + 1) ^ (row >> 1)) & 3) << 4;
        const uint32_t rbase = sb + (uint32_t)row * 64;
        float sq = 0.f;
#pragma unroll 1
        for (int c = 0; c < 8; c++) {
            const float4* s4 = (const float4*)(src + c * 32);
            float4 v0 = s4[0], v1 = s4[1], v2 = s4[2], v3 = s4[3];
            uint4 hi0, lo0, hi1, lo1;
            split8(v0, v1, hi0, lo0, sq);
            split8(v2, v3, hi1, lo1, sq);
            const uint32_t cb = rbase + c * D_CHUNK;
            *(uint4*)(smem + (cb - sb) + sw0)        = hi0;
            *(uint4*)(smem + (cb - sb) + sw1)        = hi1;
            *(uint4*)(smem + (cb - sb) + 4096 + sw0) = lo0;
            *(uint4*)(smem + (cb - sb) + 4096 + sw1) = lo1;
            size_t goff = grow * DD + c * 32 + h * 16;
            *(uint4*)(g_hi + goff)     = hi0;
            *(uint4*)(g_hi + goff + 8) = hi1;
            *(uint4*)(g_lo + goff)     = lo0;
            *(uint4*)(g_lo + goff + 8) = lo1;
        }
        sq += __shfl_xor_sync(0xFFFFFFFFu, sq, 1);
        if (h == 0) {
            ((float*)(smem + D_SQ))[row] = sq;
            g_sq[grow] = sq;
        }
    }
    __syncthreads();

    // ---- ldmatrix swizzle constants ----
    const int la = lane & 15;
    const uint32_t aro = (uint32_t)la * 64;
    const int xa = (la >> 1) & 3;
    const int pa = lane >> 4;
    const uint32_t cxa0 = (uint32_t)((pa ^ xa) & 3) << 4;
    const uint32_t cxa1 = (uint32_t)(((2 + pa) ^ xa) & 3) << 4;
    const int rbr = (lane & 7) + ((lane >> 4) & 1) * 8;
    const uint32_t bro = (uint32_t)rbr * 64;
    const int xb = (rbr >> 1) & 3;
    const int pb = (lane >> 3) & 1;
    const uint32_t cxb0 = (uint32_t)((pb ^ xb) & 3) << 4;
    const uint32_t cxb1 = (uint32_t)(((2 + pb) ^ xb) & 3) << 4;

    float acc[2][4][4];
#pragma unroll
    for (int mi = 0; mi < 2; mi++)
#pragma unroll
        for (int ni = 0; ni < 4; ni++)
#pragma unroll
            for (int r = 0; r < 4; r++) acc[mi][ni][r] = 0.f;

#pragma unroll 1
    for (int s = 0; s < 8; s++) {
        const uint32_t bufb = sb + (uint32_t)s * D_CHUNK;
#pragma unroll
        for (int ks = 0; ks < 2; ks++) {
            const uint32_t cxa = ks ? cxa1 : cxa0;
            const uint32_t cxb = ks ? cxb1 : cxb0;
            uint32_t ahi[2][4], alo[2][4], bhi[2][4], blo[2][4];
#pragma unroll
            for (int mi = 0; mi < 2; mi++) {
                uint32_t ra = bufb + (uint32_t)(wr * 32 + mi * 16) * 64 + aro + cxa;
                ldm_x4(ahi[mi], ra);
                ldm_x4(alo[mi], ra + 4096);
            }
#pragma unroll
            for (int g = 0; g < 2; g++) {
                uint32_t rbad = bufb + (uint32_t)(wc * 32 + g * 16) * 64 + bro + cxb;
                ldm_x4(bhi[g], rbad);
                ldm_x4(blo[g], rbad + 4096);
            }
#pragma unroll
            for (int mi = 0; mi < 2; mi++)
#pragma unroll
                for (int ni = 0; ni < 4; ni++) {
                    const int g = ni >> 1, o = (ni & 1) * 2;
                    mma16816(acc[mi][ni], ahi[mi], &bhi[g][o]);
                    mma16816(acc[mi][ni], ahi[mi], &blo[g][o]);
                    mma16816(acc[mi][ni], alo[mi], &bhi[g][o]);
                }
        }
    }

    // ---- diag epilogue ----
    const float* sq_s = (const float*)(smem + D_SQ);
    float rmin[4], rmax[4];
#pragma unroll
    for (int i = 0; i < 4; i++) { rmin[i] = FLT_MAX; rmax[i] = -FLT_MAX; }
    float dsum = 0.f;
#pragma unroll
    for (int mi = 0; mi < 2; mi++)
#pragma unroll
        for (int ni = 0; ni < 4; ni++)
#pragma unroll
            for (int r = 0; r < 4; r++) {
                const int rowl = wr * 32 + mi * 16 + (r >> 1) * 8 + (lane >> 2);
                const int col  = wc * 32 + ni * 8 + (lane & 3) * 2 + (r & 1);
                float d2 = sq_s[rowl] + sq_s[col] - 2.f * acc[mi][ni][r];
                float dist = sqrtf(fmaxf(d2, 0.f));
                dsum += dist;
                const int rs = mi * 2 + (r >> 1);
                if ((rowl >> 3) == (col >> 3)) rmax[rs] = fmaxf(rmax[rs], dist);
                else                           rmin[rs] = fminf(rmin[rs], dist);
            }

    float* rowmin = (float*)(smem + D_ROWMIN);
    float* rowmax = (float*)(smem + D_ROWMAX);
    float* scratch = (float*)(smem + D_RSUM);
#pragma unroll
    for (int s2 = 0; s2 < 4; s2++) {
        float rm = rmin[s2], rx = rmax[s2];
        rm = fminf(rm, __shfl_xor_sync(0xFFFFFFFFu, rm, 1));
        rm = fminf(rm, __shfl_xor_sync(0xFFFFFFFFu, rm, 2));
        rx = fmaxf(rx, __shfl_xor_sync(0xFFFFFFFFu, rx, 1));
        rx = fmaxf(rx, __shfl_xor_sync(0xFFFFFFFFu, rx, 2));
        if ((lane & 3) == 0) {
            const int row = wr * 32 + (s2 >> 1) * 16 + (s2 & 1) * 8 + (lane >> 2);
            rowmin[row * 2 + wc] = rm;
            rowmax[row * 2 + wc] = rx;
        }
    }
#pragma unroll
    for (int o = 16; o; o >>= 1) dsum += __shfl_xor_sync(0xFFFFFFFFu, dsum, o);
    if (lane == 0) scratch[wid] = dsum;
    __syncthreads();

    if (tid < 64) {
        float rn = fminf(rowmin[tid * 2], rowmin[tid * 2 + 1]);
        float rp = fmaxf(rowmax[tid * 2], rowmax[tid * 2 + 1]);
        g_min[(n * 64 + a * 8 + a) * 64 + tid] = rn;
        g_hp[n * MM + a * 64 + tid] = rp;
    }
    if (tid == 0)
        g_dsum[n * NTILE + a * (17 - a) / 2] =
            (scratch[0] + scratch[1]) + (scratch[2] + scratch[3]);
}

// ---------------------------------------------------------------------------
// Kernel 2: off-diagonal tiles (a<b) — R14 pipeline minus diag branches.
// Last CTA per part fuses the final reduction.
// ---------------------------------------------------------------------------
__global__ void __launch_bounds__(128, 6) offdiag_kernel(float* __restrict__ out) {
    extern __shared__ char smem[];
    uint32_t sb = smem_u32(smem);
    const int tid  = threadIdx.x;
    const int wid  = tid >> 5;
    const int lane = tid & 31;
    const int wr = wid >> 1;
    const int wc = wid & 1;
    const int n = blockIdx.y;
    int uu = blockIdx.x, aa = 0;
    while (uu >= 7 - aa) { uu -= 7 - aa; aa++; }
    const int a = aa, b = aa + 1 + uu;
    const int tfull = a * (17 - a) / 2 + (b - a);

    const __nv_bfloat16* hi_n = g_hi + (size_t)n * MM * DD;
    const __nv_bfloat16* lo_n = g_lo + (size_t)n * MM * DD;

    const uint32_t base_dst = sb + (uint32_t)(tid >> 2) * 64
                            + ((((uint32_t)tid & 3) ^ ((uint32_t)tid >> 3)) & 3u) * 16u;
    const size_t offA = ((size_t)a * 64 + (tid >> 2)) * DD + (tid & 3) * 8;
    const size_t offB = ((size_t)b * 64 + (tid >> 2)) * DD + (tid & 3) * 8;
    const __nv_bfloat16* hiA = hi_n + offA;
    const __nv_bfloat16* loA = lo_n + offA;
    const __nv_bfloat16* hiB = hi_n + offB;
    const __nv_bfloat16* loB = lo_n + offB;

#define LOAD_CHUNK(bufoff, k0) do {                                            \
    const uint32_t d_ = base_dst + (bufoff);                                   \
    cp16(d_ +     0, hiA + (k0));      cp16(d_ +  2048, hiA + 32*DD + (k0));   \
    cp16(d_ +  4096, loA + (k0));      cp16(d_ +  6144, loA + 32*DD + (k0));   \
    cp16(d_ +  8192, hiB + (k0));      cp16(d_ + 10240, hiB + 32*DD + (k0));   \
    cp16(d_ + 12288, loB + (k0));      cp16(d_ + 14336, loB + 32*DD + (k0));   \
} while (0)

    if (tid < 32) {
        int grp = (tid < 16) ? a : b;
        int q = tid & 15;
        cp16(sb + SM_SQ + tid * 16, g_sq + n * MM + grp * 64 + q * 4);
    }
    LOAD_CHUNK(0, 0);
    CP_COMMIT();

    const int la = lane & 15;
    const uint32_t aro = (uint32_t)la * 64;
    const int xa = (la >> 1) & 3;
    const int pa = lane >> 4;
    const uint32_t cxa0 = (uint32_t)((pa ^ xa) & 3) << 4;
    const uint32_t cxa1 = (uint32_t)(((2 + pa) ^ xa) & 3) << 4;
    const int rbr = (lane & 7) + ((lane >> 4) & 1) * 8;
    const uint32_t bro = (uint32_t)rbr * 64;
    const int xb = (rbr >> 1) & 3;
    const int pb = (lane >> 3) & 1;
    const uint32_t cxb0 = (uint32_t)((pb ^ xb) & 3) << 4;
    const uint32_t cxb1 = (uint32_t)(((2 + pb) ^ xb) & 3) << 4;

    float acc[2][4][4];
#pragma unroll
    for (int mi = 0; mi < 2; mi++)
#pragma unroll
        for (int ni = 0; ni < 4; ni++)
#pragma unroll
            for (int r = 0; r < 4; r++) acc[mi][ni][r] = 0.f;

#pragma unroll 1
    for (int s = 0; s < 8; s++) {
        if (s < 7) {
            LOAD_CHUNK(((s + 1) & 1) * BUFSZ, (s + 1) * 32);
            CP_COMMIT();
            CP_WAIT(1);
        } else {
            CP_WAIT(0);
        }
        __syncthreads();

        const uint32_t bufb = sb + (uint32_t)(s & 1) * BUFSZ;
#pragma unroll
        for (int ks = 0; ks < 2; ks++) {
            const uint32_t cxa = ks ? cxa1 : cxa0;
            const uint32_t cxb = ks ? cxb1 : cxb0;
            uint32_t ahi[2][4], alo[2][4], bhi[2][4], blo[2][4];
#pragma unroll
            for (int mi = 0; mi < 2; mi++) {
                uint32_t ra = bufb + (uint32_t)(wr * 32 + mi * 16) * 64 + aro + cxa;
                ldm_x4(ahi[mi], ra);
                ldm_x4(alo[mi], ra + PLANE);
            }
#pragma unroll
            for (int g = 0; g < 2; g++) {
                uint32_t rbad = bufb + 2u * PLANE + (uint32_t)(wc * 32 + g * 16) * 64
                              + bro + cxb;
                ldm_x4(bhi[g], rbad);
                ldm_x4(blo[g], rbad + PLANE);
            }
#pragma unroll
            for (int mi = 0; mi < 2; mi++)
#pragma unroll
                for (int ni = 0; ni < 4; ni++) {
                    const int g = ni >> 1, o = (ni & 1) * 2;
                    mma16816(acc[mi][ni], ahi[mi], &bhi[g][o]);
                    mma16816(acc[mi][ni], ahi[mi], &blo[g][o]);
                    mma16816(acc[mi][ni], alo[mi], &bhi[g][o]);
                }
        }
        __syncthreads();
    }

    // ---- epilogue (off-diag only) ----
    const float* sq_s = (const float*)(smem + SM_SQ);
    float rmin[4], cmin[8];
#pragma unroll
    for (int i = 0; i < 4; i++) rmin[i] = FLT_MAX;
#pragma unroll
    for (int i = 0; i < 8; i++) cmin[i] = FLT_MAX;
    float dsum = 0.f;

#pragma unroll
    for (int mi = 0; mi < 2; mi++)
#pragma unroll
        for (int ni = 0; ni < 4; ni++)
#pragma unroll
            for (int r = 0; r < 4; r++) {
                const int rowl = wr * 32 + mi * 16 + (r >> 1) * 8 + (lane >> 2);
                const int col  = wc * 32 + ni * 8 + (lane & 3) * 2 + (r & 1);
                float d2 = sq_s[rowl] + sq_s[64 + col] - 2.f * acc[mi][ni][r];
                float dist = sqrtf(fmaxf(d2, 0.f));
                dsum += dist;
                rmin[mi * 2 + (r >> 1)] = fminf(rmin[mi * 2 + (r >> 1)], dist);
                cmin[ni * 2 + (r & 1)]  = fminf(cmin[ni * 2 + (r & 1)], dist);
            }

    float* rowmin = (float*)(smem + SM_ROWMIN);
    float* colmin = (float*)(smem + SM_COLMIN);
    float* scratch = (float*)(smem + SM_RSUM);

#pragma unroll
    for (int s2 = 0; s2 < 4; s2++) {
        float rm = rmin[s2];
        rm = fminf(rm, __shfl_xor_sync(0xFFFFFFFFu, rm, 1));
        rm = fminf(rm, __shfl_xor_sync(0xFFFFFFFFu, rm, 2));
        if ((lane & 3) == 0) {
            const int row = wr * 32 + (s2 >> 1) * 16 + (s2 & 1) * 8 + (lane >> 2);
            rowmin[row * 2 + wc] = rm;
        }
    }
#pragma unroll
    for (int s2 = 0; s2 < 8; s2++) {
        float cm = cmin[s2];
        cm = fminf(cm, __shfl_xor_sync(0xFFFFFFFFu, cm, 4));
        cm = fminf(cm, __shfl_xor_sync(0xFFFFFFFFu, cm, 8));
        cm = fminf(cm, __shfl_xor_sync(0xFFFFFFFFu, cm, 16));
        if (lane < 4) {
            const int col = wc * 32 + (s2 >> 1) * 8 + (lane & 3) * 2 + (s2 & 1);
            colmin[col * 2 + wr] = cm;
        }
    }
#pragma unroll
    for (int o = 16; o; o >>= 1) dsum += __shfl_xor_sync(0xFFFFFFFFu, dsum, o);
    if (lane == 0) scratch[wid] = dsum;
    __syncthreads();

    if (tid < 64) {
        float rn = fminf(rowmin[tid * 2], rowmin[tid * 2 + 1]);
        g_min[(n * 64 + a * 8 + b) * 64 + tid] = rn;       // slot b of group a
    } else {
        const int j = tid - 64;
        float cm = fminf(colmin[j * 2], colmin[j * 2 + 1]);
        g_min[(n * 64 + b * 8 + a) * 64 + j] = cm;         // slot a of group b
    }
    if (tid == 0)
        g_dsum[n * NTILE + tfull] = (scratch[0] + scratch[1]) + (scratch[2] + scratch[3]);

    // ---- last-CTA-per-part fused finish ----
    int* flag = (int*)(scratch + 4);
    if (tid == 0) {
        __threadfence();
        int prev = atomicAdd(&g_cnt[n], 1);
        *flag = (prev == NOFF - 1);
    }
    __syncthreads();
    if (!*flag) return;
    __threadfence();

    float l = 0.f;
#pragma unroll
    for (int h = 0; h < 4; h++) {
        const int row = tid + h * 128;
        const int g = row >> 6, j = row & 63;
        float mn = FLT_MAX;
#pragma unroll
        for (int s = 0; s < 8; s++)
            mn = fminf(mn, g_min[(n * 64 + g * 8 + s) * 64 + j]);
        l += fmaxf(MARGIN + g_hp[n * MM + row] - mn, 0.f);
    }
#pragma unroll
    for (int o = 16; o; o >>= 1) l += __shfl_xor_sync(0xFFFFFFFFu, l, o);
    if (lane == 0) scratch[wid] = l;
    if (tid < NTILE) {
        int ax, bx; tile_pair(tid, ax, bx);
        scratch[8 + tid] = g_dsum[n * NTILE + tid] * ((ax == bx) ? 1.f : 2.f);
    }
    __syncthreads();
    if (tid == 0) {
        float ls = (scratch[0] + scratch[1]) + (scratch[2] + scratch[3]);
        float d = 0.f;
#pragma unroll
        for (int i = 0; i < NTILE; i++) d += scratch[8 + i];
        out[n]         = ls / (float)MM;
        out[NPART + n] = d / ((float)MM * (float)MM);
        g_cnt[n] = 0;   // reset for next graph replay
    }
}

extern "C" void kernel_launch(void* const* d_in, const int* in_sizes, int n_in,
                              void* d_out, int out_size) {
    const float* feature = (const float*)d_in[0];
    float* out = (float*)d_out;

    cudaFuncSetAttribute(diag_kernel, cudaFuncAttributeMaxDynamicSharedMemorySize, D_TOTAL);
    cudaFuncSetAttribute(offdiag_kernel, cudaFuncAttributeMaxDynamicSharedMemorySize, SM_TOTAL);

    dim3 g1(8, NPART);
    diag_kernel<<<g1, 128, D_TOTAL>>>(feature);

    dim3 g2(NOFF, NPART);
    offdiag_kernel<<<g2, 128, SM_TOTAL>>>(out);
}

// round 16
// speedup vs baseline: 1.1518x; 1.1518x over previous
#include <cuda_runtime.h>
#include <cuda_bf16.h>
#include <math.h>
#include <float.h>
#include <stdint.h>

#define NPART 62
#define MM    512
#define DD    256
#define MARGIN 0.2f
#define NTILE 36           // pairs (a<=b) of 8 groups of 64
#define NSLOT 12           // CTAs per part, 3 tiles each

// smem: 2 buffers x 4 planes x (64 rows x 64B, XOR-swizzled) + scratch
#define PLANE   4096       // 64 * 64
#define BUFSZ   16384      // 4 planes
#define SM_SQ     32768    // 2 x 128 floats (double-buffered by tile parity)
#define SM_ROWMIN 33792    // 64*2 f
#define SM_ROWMAX 34304    // 64*2 f
#define SM_COLMIN 34816    // 64*2 f
#define SM_RSUM   35328    // scratch (wsum / flag / finish)
#define SM_TOTAL  35840

// global scratch (no allocation allowed)
__device__ float g_min[NPART * 64 * 64];     // slot-owned mins (no init needed)
__device__ float g_hp[NPART * MM];           // written only by diagonal tiles
__device__ float g_dsum[NPART * NTILE];      // per-tile dist sums (fixed order)
__device__ int   g_cnt[NPART];               // arrival counters (reset by last CTA)
__device__ __align__(16) __nv_bfloat16 g_hi[(size_t)NPART * MM * DD];
__device__ __align__(16) __nv_bfloat16 g_lo[(size_t)NPART * MM * DD];
__device__ __align__(16) float g_sq[NPART * MM];

__device__ __forceinline__ uint32_t smem_u32(const void* p) {
    uint32_t a;
    asm("{ .reg .u64 t; cvta.to.shared.u64 t, %1; cvt.u32.u64 %0, t; }" : "=r"(a) : "l"(p));
    return a;
}
__device__ __forceinline__ void cp16(uint32_t dst, const void* src) {
    asm volatile("cp.async.cg.shared.global [%0], [%1], 16;" :: "r"(dst), "l"(src));
}
#define CP_COMMIT() asm volatile("cp.async.commit_group;" ::: "memory")
#define CP_WAIT(n)  asm volatile("cp.async.wait_group %0;" :: "n"(n) : "memory")

__device__ __forceinline__ void ldm_x4(uint32_t* r, uint32_t addr) {
    asm volatile("ldmatrix.sync.aligned.m8n8.x4.shared.b16 {%0,%1,%2,%3}, [%4];"
                 : "=r"(r[0]), "=r"(r[1]), "=r"(r[2]), "=r"(r[3]) : "r"(addr));
}
__device__ __forceinline__ void mma16816(float* c, const uint32_t* a, const uint32_t* b) {
    asm volatile("mma.sync.aligned.m16n8k16.row.col.f32.bf16.bf16.f32 "
                 "{%0,%1,%2,%3}, {%4,%5,%6,%7}, {%8,%9}, {%0,%1,%2,%3};"
                 : "+f"(c[0]), "+f"(c[1]), "+f"(c[2]), "+f"(c[3])
                 : "r"(a[0]), "r"(a[1]), "r"(a[2]), "r"(a[3]), "r"(b[0]), "r"(b[1]));
}
__device__ __forceinline__ void tile_pair(int t, int& a, int& b) {
    int aa = 0, tt = t;
    while (tt >= 8 - aa) { tt -= 8 - aa; aa++; }
    a = aa; b = aa + tt;
}
__device__ __forceinline__ void split8(float4 v0, float4 v1, uint4& hi, uint4& lo,
                                       float& sq) {
    __nv_bfloat162 h0 = __floats2bfloat162_rn(v0.x, v0.y);
    __nv_bfloat162 h1 = __floats2bfloat162_rn(v0.z, v0.w);
    __nv_bfloat162 h2 = __floats2bfloat162_rn(v1.x, v1.y);
    __nv_bfloat162 h3 = __floats2bfloat162_rn(v1.z, v1.w);
    float2 f0 = __bfloat1622float2(h0), f1 = __bfloat1622float2(h1);
    float2 f2 = __bfloat1622float2(h2), f3 = __bfloat1622float2(h3);
    __nv_bfloat162 l0 = __floats2bfloat162_rn(v0.x - f0.x, v0.y - f0.y);
    __nv_bfloat162 l1 = __floats2bfloat162_rn(v0.z - f1.x, v0.w - f1.y);
    __nv_bfloat162 l2 = __floats2bfloat162_rn(v1.x - f2.x, v1.y - f2.y);
    __nv_bfloat162 l3 = __floats2bfloat162_rn(v1.z - f3.x, v1.w - f3.y);
    hi = make_uint4(*(uint32_t*)&h0, *(uint32_t*)&h1, *(uint32_t*)&h2, *(uint32_t*)&h3);
    lo = make_uint4(*(uint32_t*)&l0, *(uint32_t*)&l1, *(uint32_t*)&l2, *(uint32_t*)&l3);
    sq += v0.x * v0.x + v0.y * v0.y + v0.z * v0.z + v0.w * v0.w
        + v1.x * v1.x + v1.y * v1.y + v1.z * v1.z + v1.w * v1.w;
}

// ---------------------------------------------------------------------------
// Kernel 1: per row: exact fp32 sq-norm + split-bf16 hi/lo (STG.128 stores).
// One warp per row; lane owns 8 consecutive floats.
// ---------------------------------------------------------------------------
__global__ void prep_kernel(const float* __restrict__ f) {
    int row = blockIdx.x * blockDim.y + threadIdx.y;
    if (row >= NPART * MM) return;
    int lane = threadIdx.x;
    const float4* p = (const float4*)(f + (size_t)row * DD) + lane * 2;
    float s = 0.f;
    uint4 hi, lo;
    split8(p[0], p[1], hi, lo, s);
    size_t off = (size_t)row * DD + lane * 8;
    *(uint4*)(g_hi + off) = hi;
    *(uint4*)(g_lo + off) = lo;
#pragma unroll
    for (int o = 16; o; o >>= 1) s += __shfl_xor_sync(0xFFFFFFFFu, s, o);
    if (lane == 0) g_sq[row] = s;
}

// ---------------------------------------------------------------------------
// Kernel 2: CTA = (slot, part n), 3 tiles per CTA (t = slot + 12j).
// Proven R14 per-tile pipeline; at s==7 the NEXT tile's chunk0 + sq are
// prefetched into buffer 0 (safe: buf0 last read at s=6, end-sync passed;
// sq double-buffered by tile parity). Fused finish (counter 12).
// ---------------------------------------------------------------------------
__global__ void __launch_bounds__(128, 6) gemm_kernel(float* __restrict__ out) {
    extern __shared__ char smem[];
    uint32_t sb = smem_u32(smem);
    const int tid  = threadIdx.x;
    const int wid  = tid >> 5;
    const int lane = tid & 31;
    const int wr = wid >> 1;
    const int wc = wid & 1;
    const int slot = blockIdx.x;
    const int n    = blockIdx.y;

    const __nv_bfloat16* hi_n = g_hi + (size_t)n * MM * DD;
    const __nv_bfloat16* lo_n = g_lo + (size_t)n * MM * DD;

    const uint32_t base_dst = sb + (uint32_t)(tid >> 2) * 64
                            + ((((uint32_t)tid & 3) ^ ((uint32_t)tid >> 3)) & 3u) * 16u;
    const size_t lane_off = (size_t)(tid >> 2) * DD + (tid & 3) * 8;

#define LOAD_CHUNK(bufoff, k0, pA, pB, dg) do {                                \
    const uint32_t d_ = base_dst + (bufoff);                                   \
    cp16(d_ +     0, hi_n + (pA) + (k0));                                      \
    cp16(d_ +  2048, hi_n + (pA) + 32*DD + (k0));                              \
    cp16(d_ +  4096, lo_n + (pA) + (k0));                                      \
    cp16(d_ +  6144, lo_n + (pA) + 32*DD + (k0));                              \
    if (!(dg)) {                                                               \
        cp16(d_ +  8192, hi_n + (pB) + (k0));                                  \
        cp16(d_ + 10240, hi_n + (pB) + 32*DD + (k0));                          \
        cp16(d_ + 12288, lo_n + (pB) + (k0));                                  \
        cp16(d_ + 14336, lo_n + (pB) + 32*DD + (k0));                          \
    }                                                                          \
} while (0)

    // per-lane ldmatrix swizzle constants (tile-invariant)
    const int la = lane & 15;
    const uint32_t aro = (uint32_t)la * 64;
    const int xa = (la >> 1) & 3;
    const int pa = lane >> 4;
    const uint32_t cxa0 = (uint32_t)((pa ^ xa) & 3) << 4;
    const uint32_t cxa1 = (uint32_t)(((2 + pa) ^ xa) & 3) << 4;
    const int rbr = (lane & 7) + ((lane >> 4) & 1) * 8;
    const uint32_t bro = (uint32_t)rbr * 64;
    const int xb = (rbr >> 1) & 3;
    const int pb = (lane >> 3) & 1;
    const uint32_t cxb0 = (uint32_t)((pb ^ xb) & 3) << 4;
    const uint32_t cxb1 = (uint32_t)(((2 + pb) ^ xb) & 3) << 4;

    float* rowmin = (float*)(smem + SM_ROWMIN);
    float* rowmax = (float*)(smem + SM_ROWMAX);
    float* colmin = (float*)(smem + SM_COLMIN);
    float* scratch = (float*)(smem + SM_RSUM);

#pragma unroll 1
    for (int j = 0; j < 3; j++) {
        const int t = slot + j * NSLOT;
        int a, b; tile_pair(t, a, b);
        const bool diag = (a == b);
        const size_t pA = (size_t)a * 64 * DD + lane_off;
        const size_t pB = (size_t)b * 64 * DD + lane_off;
        const uint32_t bplane = diag ? 0u : 2u * PLANE;
        const uint32_t sqoff = SM_SQ + (uint32_t)(j & 1) * 512;

        if (j == 0) {
            if (tid < 32) {
                int grp = (tid < 16) ? a : b;
                int q = tid & 15;
                cp16(sb + sqoff + tid * 16, g_sq + n * MM + grp * 64 + q * 4);
            }
            LOAD_CHUNK(0, 0, pA, pB, diag);
            CP_COMMIT();
        }
        // else: chunk0 + sq prefetched at previous tile's s==7

        float acc[2][4][4];
#pragma unroll
        for (int mi = 0; mi < 2; mi++)
#pragma unroll
            for (int ni = 0; ni < 4; ni++)
#pragma unroll
                for (int r = 0; r < 4; r++) acc[mi][ni][r] = 0.f;

#pragma unroll 1
        for (int s = 0; s < 8; s++) {
            if (s < 7) {
                LOAD_CHUNK(((s + 1) & 1) * BUFSZ, (s + 1) * 32, pA, pB, diag);
                CP_COMMIT();
                CP_WAIT(1);
            } else if (j < 2) {
                // prefetch next tile's chunk0 (buffer 0) + its sq
                const int t2 = slot + (j + 1) * NSLOT;
                int a2, b2; tile_pair(t2, a2, b2);
                const bool dg2 = (a2 == b2);
                const size_t pA2 = (size_t)a2 * 64 * DD + lane_off;
                const size_t pB2 = (size_t)b2 * 64 * DD + lane_off;
                if (tid < 32) {
                    int grp = (tid < 16) ? a2 : b2;
                    int q = tid & 15;
                    cp16(sb + SM_SQ + (uint32_t)((j + 1) & 1) * 512 + tid * 16,
                         g_sq + n * MM + grp * 64 + q * 4);
                }
                LOAD_CHUNK(0, 0, pA2, pB2, dg2);
                CP_COMMIT();
                CP_WAIT(1);
            } else {
                CP_WAIT(0);
            }
            __syncthreads();

            const uint32_t bufb = sb + (uint32_t)(s & 1) * BUFSZ;
#pragma unroll
            for (int ks = 0; ks < 2; ks++) {
                const uint32_t cxa = ks ? cxa1 : cxa0;
                const uint32_t cxb = ks ? cxb1 : cxb0;
                uint32_t ahi[2][4], alo[2][4], bhi[2][4], blo[2][4];
#pragma unroll
                for (int mi = 0; mi < 2; mi++) {
                    uint32_t ra = bufb + (uint32_t)(wr * 32 + mi * 16) * 64 + aro + cxa;
                    ldm_x4(ahi[mi], ra);
                    ldm_x4(alo[mi], ra + PLANE);
                }
#pragma unroll
                for (int g = 0; g < 2; g++) {
                    uint32_t rbad = bufb + bplane + (uint32_t)(wc * 32 + g * 16) * 64
                                  + bro + cxb;
                    ldm_x4(bhi[g], rbad);
                    ldm_x4(blo[g], rbad + PLANE);
                }
#pragma unroll
                for (int mi = 0; mi < 2; mi++)
#pragma unroll
                    for (int ni = 0; ni < 4; ni++) {
                        const int g = ni >> 1, o = (ni & 1) * 2;
                        mma16816(acc[mi][ni], ahi[mi], &bhi[g][o]);
                        mma16816(acc[mi][ni], ahi[mi], &blo[g][o]);
                        mma16816(acc[mi][ni], alo[mi], &bhi[g][o]);
                    }
            }
            __syncthreads();   // all warps done reading buf s&1 before refill
        }

        // ---- epilogue (per tile) ----
        const float* sq_s = (const float*)(smem + sqoff);
        float rmin[4], rmax[4], cmin[8];
#pragma unroll
        for (int i = 0; i < 4; i++) { rmin[i] = FLT_MAX; rmax[i] = -FLT_MAX; }
#pragma unroll
        for (int i = 0; i < 8; i++) cmin[i] = FLT_MAX;
        float dsum = 0.f;

#pragma unroll
        for (int mi = 0; mi < 2; mi++)
#pragma unroll
            for (int ni = 0; ni < 4; ni++)
#pragma unroll
                for (int r = 0; r < 4; r++) {
                    const int rowl = wr * 32 + mi * 16 + (r >> 1) * 8 + (lane >> 2);
                    const int col  = wc * 32 + ni * 8 + (lane & 3) * 2 + (r & 1);
                    float d2 = sq_s[rowl] + sq_s[64 + col] - 2.f * acc[mi][ni][r];
                    float dist = sqrtf(fmaxf(d2, 0.f));
                    dsum += dist;
                    const int rs = mi * 2 + (r >> 1);
                    const int cs = ni * 2 + (r & 1);
                    if (diag) {
                        if ((rowl >> 3) == (col >> 3)) rmax[rs] = fmaxf(rmax[rs], dist);
                        else                           rmin[rs] = fminf(rmin[rs], dist);
                    } else {
                        rmin[rs] = fminf(rmin[rs], dist);
                        cmin[cs] = fminf(cmin[cs], dist);
                    }
                }

#pragma unroll
        for (int s2 = 0; s2 < 4; s2++) {
            float rm = rmin[s2], rx = rmax[s2];
            rm = fminf(rm, __shfl_xor_sync(0xFFFFFFFFu, rm, 1));
            rm = fminf(rm, __shfl_xor_sync(0xFFFFFFFFu, rm, 2));
            rx = fmaxf(rx, __shfl_xor_sync(0xFFFFFFFFu, rx, 1));
            rx = fmaxf(rx, __shfl_xor_sync(0xFFFFFFFFu, rx, 2));
            if ((lane & 3) == 0) {
                const int row = wr * 32 + (s2 >> 1) * 16 + (s2 & 1) * 8 + (lane >> 2);
                rowmin[row * 2 + wc] = rm;
                rowmax[row * 2 + wc] = rx;
            }
        }
#pragma unroll
        for (int s2 = 0; s2 < 8; s2++) {
            float cm = cmin[s2];
            cm = fminf(cm, __shfl_xor_sync(0xFFFFFFFFu, cm, 4));
            cm = fminf(cm, __shfl_xor_sync(0xFFFFFFFFu, cm, 8));
            cm = fminf(cm, __shfl_xor_sync(0xFFFFFFFFu, cm, 16));
            if (lane < 4) {
                const int col = wc * 32 + (s2 >> 1) * 8 + (lane & 3) * 2 + (s2 & 1);
                colmin[col * 2 + wr] = cm;
            }
        }
#pragma unroll
        for (int o = 16; o; o >>= 1) dsum += __shfl_xor_sync(0xFFFFFFFFu, dsum, o);
        if (lane == 0) scratch[wid] = dsum;
        __syncthreads();

        if (tid < 64) {
            float rn = fminf(rowmin[tid * 2], rowmin[tid * 2 + 1]);
            float rp = fmaxf(rowmax[tid * 2], rowmax[tid * 2 + 1]);
            g_min[(n * 64 + a * 8 + b) * 64 + tid] = rn;   // slot b of group a
            if (diag) g_hp[n * MM + a * 64 + tid] = rp;
        } else {
            if (!diag) {
                const int jj = tid - 64;
                float cm = fminf(colmin[jj * 2], colmin[jj * 2 + 1]);
                g_min[(n * 64 + b * 8 + a) * 64 + jj] = cm; // slot a of group b
            }
        }
        if (tid == 0)
            g_dsum[n * NTILE + t] = (scratch[0] + scratch[1]) + (scratch[2] + scratch[3]);
        __syncthreads();   // reduction smem free before next tile reuses it
    }

    // ---- last-CTA-per-part fused finish ----
    int* flag = (int*)(scratch + 4);
    if (tid == 0) {
        __threadfence();
        int prev = atomicAdd(&g_cnt[n], 1);
        *flag = (prev == NSLOT - 1);
    }
    __syncthreads();
    if (!*flag) return;
    __threadfence();

    float l = 0.f;
#pragma unroll
    for (int h = 0; h < 4; h++) {
        const int row = tid + h * 128;
        const int g = row >> 6, jj = row & 63;
        float mn = FLT_MAX;
#pragma unroll
        for (int s = 0; s < 8; s++)
            mn = fminf(mn, g_min[(n * 64 + g * 8 + s) * 64 + jj]);
        l += fmaxf(MARGIN + g_hp[n * MM + row] - mn, 0.f);
    }
#pragma unroll
    for (int o = 16; o; o >>= 1) l += __shfl_xor_sync(0xFFFFFFFFu, l, o);
    if (lane == 0) scratch[wid] = l;
    if (tid < NTILE) {
        int aa, bb; tile_pair(tid, aa, bb);
        scratch[8 + tid] = g_dsum[n * NTILE + tid] * ((aa == bb) ? 1.f : 2.f);
    }
    __syncthreads();
    if (tid == 0) {
        float ls = (scratch[0] + scratch[1]) + (scratch[2] + scratch[3]);
        float d = 0.f;
#pragma unroll
        for (int i = 0; i < NTILE; i++) d += scratch[8 + i];
        out[n]         = ls / (float)MM;
        out[NPART + n] = d / ((float)MM * (float)MM);
        g_cnt[n] = 0;   // reset for next graph replay
    }
}

extern "C" void kernel_launch(void* const* d_in, const int* in_sizes, int n_in,
                              void* d_out, int out_size) {
    const float* feature = (const float*)d_in[0];
    float* out = (float*)d_out;

    cudaFuncSetAttribute(gemm_kernel, cudaFuncAttributeMaxDynamicSharedMemorySize, SM_TOTAL);

    dim3 b1(32, 8);
    prep_kernel<<<(NPART * MM + 7) / 8, b1>>>(feature);

    dim3 grid(NSLOT, NPART);
    gemm_kernel<<<grid, 128, SM_TOTAL>>>(out);
}